// round 17
// baseline (speedup 1.0000x reference)
#include <cuda_runtime.h>
#include <cuda_bf16.h>
#include <cuda_fp16.h>
#include <cstdint>
#include <math.h>

#define N_NODES 10000
#define F 256
#define E_POS 320000
#define E_TOT 330000
#define E_EVAL 100000
#define NEG_SLOPE 0.2f
#define EPS_F 1e-16f
#define SLOT_CAP 128

// ---------------- scratch (device globals; zero-initialized at load) ----------------
// g_deg / g_als* / g_ald* / g_bc rely on zero-init for the FIRST call and are
// re-zeroed at the tail of dot_kernel so every call sees identical state.
__device__ __half g_xH[N_NODES * F];      // x in fp16 (gemm1 A operand)
__device__ __half g_h1H[N_NODES * F];     // aggregate1 out (gemm2 A operand)
__device__ __half g_bufH[N_NODES * F];    // gemm fp16 out (aggregate gather source)
__device__ __half g_hOut[N_NODES * F];    // aggregate2 out (dot source)
__device__ float g_als1[N_NODES];
__device__ float g_ald1[N_NODES];
__device__ float g_als2[N_NODES];
__device__ float g_ald2[N_NODES];
__device__ float g_bc[F];                 // folded bias Win_b @ W1
__device__ int   g_deg[N_NODES];
__device__ int   g_srcs[N_NODES * SLOT_CAP];
__device__ __nv_bfloat16 g_Xh[F * F];     // Win_W split, row-major [m][k] (fold A)
__device__ __nv_bfloat16 g_Xl[F * F];
__device__ __nv_bfloat16 g_W1h[F * F];    // W1 split, transposed [n][k] (fold B)
__device__ __nv_bfloat16 g_W1l[F * F];
__device__ __half g_WcH[F * F];           // fold result Wc, fp16 [n][k]
__device__ __half g_W2H[F * F];           // W2, fp16 [n][k]

#define SW128(o) ((o) ^ (((o) >> 3) & 0x70))

__device__ __forceinline__ uint32_t smem_to_u32(const void* p) {
    uint32_t a;
    asm("{ .reg .u64 t; cvta.to.shared.u64 t, %1; cvt.u32.u64 %0, t; }"
        : "=r"(a) : "l"(p));
    return a;
}
__device__ __forceinline__ void ldsm_x4(uint32_t* r, uint32_t addr) {
    asm volatile("ldmatrix.sync.aligned.m8n8.x4.shared.b16 {%0,%1,%2,%3}, [%4];"
        : "=r"(r[0]), "=r"(r[1]), "=r"(r[2]), "=r"(r[3]) : "r"(addr));
}
__device__ __forceinline__ void mma_bf16(float* c, const uint32_t* a, const uint32_t* b) {
    asm volatile(
        "mma.sync.aligned.m16n8k16.row.col.f32.bf16.bf16.f32 "
        "{%0,%1,%2,%3}, {%4,%5,%6,%7}, {%8,%9}, {%0,%1,%2,%3};"
        : "+f"(c[0]), "+f"(c[1]), "+f"(c[2]), "+f"(c[3])
        : "r"(a[0]), "r"(a[1]), "r"(a[2]), "r"(a[3]), "r"(b[0]), "r"(b[1]));
}
__device__ __forceinline__ void mma_f16(float* c, const uint32_t* a, const uint32_t* b) {
    asm volatile(
        "mma.sync.aligned.m16n8k16.row.col.f32.f16.f16.f32 "
        "{%0,%1,%2,%3}, {%4,%5,%6,%7}, {%8,%9}, {%0,%1,%2,%3};"
        : "+f"(c[0]), "+f"(c[1]), "+f"(c[2]), "+f"(c[3])
        : "r"(a[0]), "r"(a[1]), "r"(a[2]), "r"(a[3]), "r"(b[0]), "r"(b[1]));
}
__device__ __forceinline__ void cp_async16(uint32_t saddr, const void* g, bool valid) {
    int sz = valid ? 16 : 0;
    asm volatile("cp.async.cg.shared.global [%0], [%1], 16, %2;"
        :: "r"(saddr), "l"(g), "r"(sz) : "memory");
}
#define CP_COMMIT() asm volatile("cp.async.commit_group;" ::: "memory")
#define CP_WAIT(n)  asm volatile("cp.async.wait_group %0;" :: "n"(n) : "memory")

// ---------------- fused independent work ----------------
#define E_Q (E_TOT / 4)                          // 82500
#define SC_B ((E_Q + 255) / 256)                 // 323
#define X16_N (N_NODES * F / 8)                  // 320000 (8 floats/thread)
#define SP_B ((X16_N + 3 * F * F + 255) / 256)
#define FB_B (F / 32)                            // 8
#define WORK_B (SC_B + SP_B + FB_B)

__global__ void work_kernel(const int* __restrict__ pos_ei,
                            const float* __restrict__ x,
                            const float* __restrict__ WinW,
                            const float* __restrict__ W1,
                            const float* __restrict__ W2,
                            const float* __restrict__ Win_b) {
    int b = blockIdx.x;
    if (b < SC_B) {
        int gid = b * blockDim.x + threadIdx.x;
        if (gid >= E_Q) return;
        #pragma unroll
        for (int q = 0; q < 4; q++) {
            int e = gid + q * E_Q;
            int src, dst;
            if (e < E_POS) { src = __ldg(pos_ei + e); dst = __ldg(pos_ei + E_POS + e); }
            else           { src = e - E_POS; dst = src; }
            int pos = atomicAdd(&g_deg[dst], 1);
            if (pos < SLOT_CAP) g_srcs[dst * SLOT_CAP + pos] = src;
        }
    } else if (b < SC_B + SP_B) {
        int idx = (b - SC_B) * blockDim.x + threadIdx.x;
        if (idx < X16_N) {
            float4 v0 = reinterpret_cast<const float4*>(x)[idx * 2];
            float4 v1 = reinterpret_cast<const float4*>(x)[idx * 2 + 1];
            __half2 h[4] = {
                __floats2half2_rn(v0.x, v0.y), __floats2half2_rn(v0.z, v0.w),
                __floats2half2_rn(v1.x, v1.y), __floats2half2_rn(v1.z, v1.w) };
            reinterpret_cast<uint4*>(g_xH)[idx] = *reinterpret_cast<uint4*>(h);
        } else {
            int i2 = idx - X16_N;
            if (i2 < 3 * F * F) {
                int w = i2 >> 16;
                int j = i2 & 65535;
                int k = j >> 8, n = j & 255;
                if (w == 0) {
                    float v = __ldg(WinW + j);
                    __nv_bfloat16 h = __float2bfloat16(v);
                    g_Xh[j] = h;
                    g_Xl[j] = __float2bfloat16(v - __bfloat162float(h));
                } else if (w == 1) {
                    float v = __ldg(W1 + j);
                    __nv_bfloat16 h = __float2bfloat16(v);
                    g_W1h[n * F + k] = h;
                    g_W1l[n * F + k] = __float2bfloat16(v - __bfloat162float(h));
                } else {
                    g_W2H[n * F + k] = __float2half(__ldg(W2 + j));
                }
            }
        }
    } else {
        int n = threadIdx.x;
        int k0 = (b - SC_B - SP_B) * 32;
        float s = 0.f;
        #pragma unroll
        for (int kk = 0; kk < 32; kk++) {
            int k = k0 + kk;
            s = fmaf(__ldg(Win_b + k), __ldg(W1 + (size_t)k * F + n), s);
        }
        atomicAdd(&g_bc[n], s);
    }
}

// ---------------- fold GEMM (bf16 3-term): Wc = Win_W @ W1 -> fp16 [n][k] ----------------
#define SA_H 0
#define SA_L 8192
#define SB_H 16384
#define SB_L 32768
#define STAGE_BYTES 49152
#define SMEM_FOLD (2 * STAGE_BYTES + 1024)

__global__ __launch_bounds__(256, 2) void gemm_fold_kernel(
    const __nv_bfloat16* __restrict__ Ah, const __nv_bfloat16* __restrict__ Al,
    const __nv_bfloat16* __restrict__ Bh, const __nv_bfloat16* __restrict__ Bl,
    int M) {
    extern __shared__ char dsmem[];
    const int tid = threadIdx.x;
    const int wid = tid >> 5;
    const int lane = tid & 31;
    const int wm = wid >> 2;
    const int wn = wid & 3;
    const int row0 = blockIdx.y * 64;
    const int col0 = blockIdx.x * 128;

    uint32_t dsb = smem_to_u32(dsmem);
    uint32_t sb = (dsb + 1023) & ~1023u;

    float acc[2][4][4] = {};

    const int a_row = wm * 32 + (lane & 15);
    const int a_kb  = (lane >> 4) * 16;
    const int b_row = wn * 32 + (lane & 7) + ((lane >> 4) & 1) * 8;
    const int b_kb  = ((lane >> 3) & 1) * 16;

    const __nv_bfloat16* opsA[2] = { Ah, Al };
    const __nv_bfloat16* opsB[2] = { Bh, Bl };
    const int boffA[2] = { SA_H, SA_L };
    const int boffB[2] = { SB_H, SB_L };

    const int lr = tid >> 3;
    const int lj = tid & 7;

    #define LOAD_STAGE_F(cc, ss) do {                                            \
        uint32_t stb = sb + (ss) * STAGE_BYTES;                                   \
        _Pragma("unroll")                                                         \
        for (int t = 0; t < 2; t++) {                                             \
            _Pragma("unroll")                                                     \
            for (int it = 0; it < 2; it++) {                                      \
                int r = lr + it * 32;                                             \
                int grow = row0 + r;                                              \
                uint32_t off = SW128((uint32_t)(r * 128 + lj * 16));              \
                cp_async16(stb + boffA[t] + off,                                  \
                           opsA[t] + (size_t)grow * F + (cc) * 64 + lj * 8,       \
                           grow < M);                                             \
            }                                                                     \
        }                                                                         \
        _Pragma("unroll")                                                         \
        for (int t = 0; t < 2; t++) {                                             \
            _Pragma("unroll")                                                     \
            for (int it = 0; it < 4; it++) {                                      \
                int r = lr + it * 32;                                             \
                uint32_t off = SW128((uint32_t)(r * 128 + lj * 16));              \
                cp_async16(stb + boffB[t] + off,                                  \
                           opsB[t] + (size_t)(col0 + r) * F + (cc) * 64 + lj * 8, \
                           true);                                                 \
            }                                                                     \
        }                                                                         \
        CP_COMMIT();                                                              \
    } while (0)

    LOAD_STAGE_F(0, 0);

    #pragma unroll
    for (int c = 0; c < 4; c++) {
        CP_WAIT(0);
        __syncthreads();
        if (c + 1 < 4) LOAD_STAGE_F(c + 1, (c + 1) & 1);
        uint32_t stb = sb + (c & 1) * STAGE_BYTES;
        #pragma unroll
        for (int ks = 0; ks < 4; ks++) {
            uint32_t ah[2][4], al[2][4], bh[2][4], bl[2][4];
            #pragma unroll
            for (int mt = 0; mt < 2; mt++) {
                uint32_t off = SW128((uint32_t)((a_row + mt * 16) * 128 + ks * 32 + a_kb));
                ldsm_x4(ah[mt], stb + SA_H + off);
                ldsm_x4(al[mt], stb + SA_L + off);
            }
            #pragma unroll
            for (int ntp = 0; ntp < 2; ntp++) {
                uint32_t off = SW128((uint32_t)((b_row + ntp * 16) * 128 + ks * 32 + b_kb));
                ldsm_x4(bh[ntp], stb + SB_H + off);
                ldsm_x4(bl[ntp], stb + SB_L + off);
            }
            #pragma unroll
            for (int mt = 0; mt < 2; mt++)
                #pragma unroll
                for (int n8 = 0; n8 < 4; n8++) {
                    const uint32_t* bhf = &bh[n8 >> 1][(n8 & 1) * 2];
                    const uint32_t* blf = &bl[n8 >> 1][(n8 & 1) * 2];
                    mma_bf16(acc[mt][n8], ah[mt], bhf);
                    mma_bf16(acc[mt][n8], ah[mt], blf);
                    mma_bf16(acc[mt][n8], al[mt], bhf);
                }
        }
        __syncthreads();
    }
    #undef LOAD_STAGE_F

    #pragma unroll
    for (int mt = 0; mt < 2; mt++) {
        #pragma unroll
        for (int half = 0; half < 2; half++) {
            int gr = row0 + wm * 32 + mt * 16 + (lane >> 2) + half * 8;
            if (gr >= M) continue;
            #pragma unroll
            for (int n8 = 0; n8 < 4; n8++) {
                int gc = col0 + wn * 32 + n8 * 8 + (lane & 3) * 2;
                g_WcH[(size_t)gc * F + gr]       = __float2half(acc[mt][n8][half * 2 + 0]);
                g_WcH[(size_t)(gc + 1) * F + gr] = __float2half(acc[mt][n8][half * 2 + 1]);
            }
        }
    }
}

// ---------------- single-term fp16 GEMM ----------------
#define G16_SA 0
#define G16_SB 8192
#define G16_STAGE 24576
#define SMEM_G16 (2 * G16_STAGE + 1024)

__global__ __launch_bounds__(256, 2) void gemm16_kernel(
    const __half* __restrict__ A, const __half* __restrict__ B,
    const float* __restrict__ bias,
    const float* __restrict__ a_src, const float* __restrict__ a_dst,
    float* __restrict__ als, float* __restrict__ ald,
    __half* __restrict__ out_h, int M) {
    extern __shared__ char dsmem[];
    const int tid = threadIdx.x;
    const int wid = tid >> 5;
    const int lane = tid & 31;
    const int wm = wid >> 2;
    const int wn = wid & 3;
    const int row0 = blockIdx.y * 64;
    const int col0 = blockIdx.x * 128;

    uint32_t dsb = smem_to_u32(dsmem);
    uint32_t sb = (dsb + 1023) & ~1023u;

    float acc[2][4][4] = {};

    const int a_row = wm * 32 + (lane & 15);
    const int a_kb  = (lane >> 4) * 16;
    const int b_row = wn * 32 + (lane & 7) + ((lane >> 4) & 1) * 8;
    const int b_kb  = ((lane >> 3) & 1) * 16;

    const int lr = tid >> 3;
    const int lj = tid & 7;

    #define LOAD_STAGE16(cc, ss) do {                                             \
        uint32_t stb = sb + (ss) * G16_STAGE;                                     \
        _Pragma("unroll")                                                         \
        for (int it = 0; it < 2; it++) {                                          \
            int r = lr + it * 32;                                                 \
            int grow = row0 + r;                                                  \
            uint32_t off = SW128((uint32_t)(r * 128 + lj * 16));                  \
            cp_async16(stb + G16_SA + off,                                        \
                       A + (size_t)grow * F + (cc) * 64 + lj * 8, grow < M);      \
        }                                                                         \
        _Pragma("unroll")                                                         \
        for (int it = 0; it < 4; it++) {                                          \
            int r = lr + it * 32;                                                 \
            uint32_t off = SW128((uint32_t)(r * 128 + lj * 16));                  \
            cp_async16(stb + G16_SB + off,                                        \
                       B + (size_t)(col0 + r) * F + (cc) * 64 + lj * 8, true);    \
        }                                                                         \
        CP_COMMIT();                                                              \
    } while (0)

    uint32_t ah[2][2][4], bh[2][2][4];

    #define LDFRAGS16(stb, ks, q) do {                                            \
        _Pragma("unroll")                                                         \
        for (int mt = 0; mt < 2; mt++) {                                          \
            uint32_t off = SW128((uint32_t)((a_row + mt * 16) * 128 + (ks) * 32 + a_kb)); \
            ldsm_x4(ah[q][mt], (stb) + G16_SA + off);                             \
        }                                                                         \
        _Pragma("unroll")                                                         \
        for (int ntp = 0; ntp < 2; ntp++) {                                       \
            uint32_t off = SW128((uint32_t)((b_row + ntp * 16) * 128 + (ks) * 32 + b_kb)); \
            ldsm_x4(bh[q][ntp], (stb) + G16_SB + off);                            \
        }                                                                         \
    } while (0)

    LOAD_STAGE16(0, 0);

    #pragma unroll
    for (int c = 0; c < 4; c++) {
        CP_WAIT(0);
        __syncthreads();
        if (c + 1 < 4) LOAD_STAGE16(c + 1, (c + 1) & 1);
        uint32_t stb = sb + (c & 1) * G16_STAGE;
        LDFRAGS16(stb, 0, 0);
        #pragma unroll
        for (int ks = 0; ks < 4; ks++) {
            if (ks + 1 < 4) LDFRAGS16(stb, ks + 1, (ks + 1) & 1);
            const int q = ks & 1;
            #pragma unroll
            for (int mt = 0; mt < 2; mt++)
                #pragma unroll
                for (int n8 = 0; n8 < 4; n8++)
                    mma_f16(acc[mt][n8], ah[q][mt], &bh[q][n8 >> 1][(n8 & 1) * 2]);
        }
    }
    #undef LOAD_STAGE16
    #undef LDFRAGS16

    // ---- epilogue ----
    #pragma unroll
    for (int mt = 0; mt < 2; mt++) {
        #pragma unroll
        for (int half = 0; half < 2; half++) {
            int gr = row0 + wm * 32 + mt * 16 + (lane >> 2) + half * 8;
            bool rowok = gr < M;
            float ps = 0.f, pd = 0.f;
            #pragma unroll
            for (int n8 = 0; n8 < 4; n8++) {
                int gc = col0 + wn * 32 + n8 * 8 + (lane & 3) * 2;
                float v0 = acc[mt][n8][half * 2 + 0];
                float v1 = acc[mt][n8][half * 2 + 1];
                if (bias) { v0 += __ldg(bias + gc); v1 += __ldg(bias + gc + 1); }
                if (rowok) {
                    size_t base = (size_t)gr * F + gc;
                    *reinterpret_cast<__half2*>(out_h + base) = __floats2half2_rn(v0, v1);
                    ps += v0 * __ldg(a_src + gc) + v1 * __ldg(a_src + gc + 1);
                    pd += v0 * __ldg(a_dst + gc) + v1 * __ldg(a_dst + gc + 1);
                }
            }
            ps += __shfl_xor_sync(0xffffffffu, ps, 1);
            ps += __shfl_xor_sync(0xffffffffu, ps, 2);
            pd += __shfl_xor_sync(0xffffffffu, pd, 1);
            pd += __shfl_xor_sync(0xffffffffu, pd, 2);
            if (rowok && (lane & 3) == 0) {
                atomicAdd(&als[gr], ps);
                atomicAdd(&ald[gr], pd);
            }
        }
    }
}

// ---------------- GAT aggregation: warp per destination node ----------------
// 2-way unrolled zero-load feature loop (2 independent LDG.128 in flight)
__global__ void aggregate_kernel(const __half* __restrict__ hH,
                                 const float* __restrict__ bias,
                                 const float* __restrict__ als,
                                 const float* __restrict__ ald_arr,
                                 __half* __restrict__ out_h) {
    int node = (blockIdx.x * blockDim.x + threadIdx.x) >> 5;
    int lane = threadIdx.x & 31;
    if (node >= N_NODES) return;
    int beg = node * SLOT_CAP;
    int deg = g_deg[node];
    float ald = ald_arr[node];

    float el[4];
    int   sl[4];
    float m = -INFINITY;
    #pragma unroll
    for (int k = 0; k < 4; k++) {
        int idx = lane + k * 32;
        if (idx < deg) {
            int s0 = g_srcs[beg + idx];
            sl[k] = s0;
            float e = als[s0] + ald;
            e = (e > 0.f) ? e : NEG_SLOPE * e;
            el[k] = e;
            m = fmaxf(m, e);
        } else { sl[k] = 0; el[k] = -INFINITY; }
    }
    #pragma unroll
    for (int o = 16; o > 0; o >>= 1) m = fmaxf(m, __shfl_xor_sync(0xffffffffu, m, o));
    float wl[4];
    float s = 0.f;
    #pragma unroll
    for (int k = 0; k < 4; k++) {
        float w = (el[k] == -INFINITY) ? 0.f : __expf(el[k] - m);
        wl[k] = w;
        s += w;
    }
    #pragma unroll
    for (int o = 16; o > 0; o >>= 1) s += __shfl_xor_sync(0xffffffffu, s, o);
    float inv = 1.f / (s + EPS_F);

    // feature pass: 2-way unrolled (two loads in flight per warp-iteration)
    float4 acc0 = make_float4(0.f, 0.f, 0.f, 0.f);
    float4 acc1 = make_float4(0.f, 0.f, 0.f, 0.f);
    float4 acc2 = make_float4(0.f, 0.f, 0.f, 0.f);
    float4 acc3 = make_float4(0.f, 0.f, 0.f, 0.f);
    const uint4* hp4 = reinterpret_cast<const uint4*>(hH);
    #pragma unroll
    for (int k = 0; k < 4; k++) {
        int base_j = k * 32;
        if (base_j >= deg) break;
        int cnt = min(32, deg - base_j);
        int t = 0;
        for (; t + 2 <= cnt; t += 2) {
            float w0 = __shfl_sync(0xffffffffu, wl[k], t);
            int   s0 = __shfl_sync(0xffffffffu, sl[k], t);
            float w1 = __shfl_sync(0xffffffffu, wl[k], t + 1);
            int   s1 = __shfl_sync(0xffffffffu, sl[k], t + 1);
            uint4 v0 = __ldg(hp4 + (size_t)s0 * 32 + lane);
            uint4 v1 = __ldg(hp4 + (size_t)s1 * 32 + lane);
            const __half2* p0 = reinterpret_cast<const __half2*>(&v0);
            const __half2* p1 = reinterpret_cast<const __half2*>(&v1);
            float2 a0 = __half22float2(p0[0]); float2 a1 = __half22float2(p0[1]);
            float2 a2 = __half22float2(p0[2]); float2 a3 = __half22float2(p0[3]);
            float2 b0 = __half22float2(p1[0]); float2 b1 = __half22float2(p1[1]);
            float2 b2 = __half22float2(p1[2]); float2 b3 = __half22float2(p1[3]);
            acc0.x = fmaf(w0, a0.x, acc0.x); acc0.y = fmaf(w0, a0.y, acc0.y);
            acc0.z = fmaf(w0, a1.x, acc0.z); acc0.w = fmaf(w0, a1.y, acc0.w);
            acc1.x = fmaf(w0, a2.x, acc1.x); acc1.y = fmaf(w0, a2.y, acc1.y);
            acc1.z = fmaf(w0, a3.x, acc1.z); acc1.w = fmaf(w0, a3.y, acc1.w);
            acc2.x = fmaf(w1, b0.x, acc2.x); acc2.y = fmaf(w1, b0.y, acc2.y);
            acc2.z = fmaf(w1, b1.x, acc2.z); acc2.w = fmaf(w1, b1.y, acc2.w);
            acc3.x = fmaf(w1, b2.x, acc3.x); acc3.y = fmaf(w1, b2.y, acc3.y);
            acc3.z = fmaf(w1, b3.x, acc3.z); acc3.w = fmaf(w1, b3.y, acc3.w);
        }
        if (t < cnt) {
            float w0 = __shfl_sync(0xffffffffu, wl[k], t);
            int   s0 = __shfl_sync(0xffffffffu, sl[k], t);
            uint4 v0 = __ldg(hp4 + (size_t)s0 * 32 + lane);
            const __half2* p0 = reinterpret_cast<const __half2*>(&v0);
            float2 a0 = __half22float2(p0[0]); float2 a1 = __half22float2(p0[1]);
            float2 a2 = __half22float2(p0[2]); float2 a3 = __half22float2(p0[3]);
            acc0.x = fmaf(w0, a0.x, acc0.x); acc0.y = fmaf(w0, a0.y, acc0.y);
            acc0.z = fmaf(w0, a1.x, acc0.z); acc0.w = fmaf(w0, a1.y, acc0.w);
            acc1.x = fmaf(w0, a2.x, acc1.x); acc1.y = fmaf(w0, a2.y, acc1.y);
            acc1.z = fmaf(w0, a3.x, acc1.z); acc1.w = fmaf(w0, a3.y, acc1.w);
        }
    }
    acc0.x += acc2.x; acc0.y += acc2.y; acc0.z += acc2.z; acc0.w += acc2.w;
    acc1.x += acc3.x; acc1.y += acc3.y; acc1.z += acc3.z; acc1.w += acc3.w;

    size_t base = (size_t)node * F + (size_t)lane * 8;
    const float* bp = bias + lane * 8;
    __half2 oh[4] = {
        __floats2half2_rn(acc0.x * inv + __ldg(bp + 0), acc0.y * inv + __ldg(bp + 1)),
        __floats2half2_rn(acc0.z * inv + __ldg(bp + 2), acc0.w * inv + __ldg(bp + 3)),
        __floats2half2_rn(acc1.x * inv + __ldg(bp + 4), acc1.y * inv + __ldg(bp + 5)),
        __floats2half2_rn(acc1.z * inv + __ldg(bp + 6), acc1.w * inv + __ldg(bp + 7)) };
    *reinterpret_cast<uint4*>(out_h + base) = *reinterpret_cast<uint4*>(oh);
}

// ---------------- eval-edge dot products (fp16 inputs) + state restore ----------------
#define DOT_B ((E_EVAL * 32 + 255) / 256)     // 12500
#define CLEAN_ELEMS (5 * N_NODES + F)
#define CLEAN_B ((CLEAN_ELEMS + 2047) / 2048) // 25
__global__ void dot_kernel(const __half* __restrict__ h,
                           const int* __restrict__ ei,
                           float* __restrict__ out) {
    int b = blockIdx.x;
    if (b >= DOT_B) {
        int base = (b - DOT_B) * 2048 + threadIdx.x;
        #pragma unroll
        for (int q = 0; q < 8; q++) {
            int i = base + q * 256;
            if (i < N_NODES) g_deg[i] = 0;
            else if (i < 2 * N_NODES) g_als1[i - N_NODES] = 0.f;
            else if (i < 3 * N_NODES) g_ald1[i - 2 * N_NODES] = 0.f;
            else if (i < 4 * N_NODES) g_als2[i - 3 * N_NODES] = 0.f;
            else if (i < 5 * N_NODES) g_ald2[i - 4 * N_NODES] = 0.f;
            else if (i < 5 * N_NODES + F) g_bc[i - 5 * N_NODES] = 0.f;
        }
        return;
    }
    int eid = (b * blockDim.x + threadIdx.x) >> 5;
    int lane = threadIdx.x & 31;
    if (eid >= E_EVAL) return;
    int a = ei[eid];
    int bb = ei[E_EVAL + eid];
    uint4 va = __ldg(reinterpret_cast<const uint4*>(h + (size_t)a * F) + lane);
    uint4 vb = __ldg(reinterpret_cast<const uint4*>(h + (size_t)bb * F) + lane);
    const __half2* pa = reinterpret_cast<const __half2*>(&va);
    const __half2* pb = reinterpret_cast<const __half2*>(&vb);
    float s = 0.f;
    #pragma unroll
    for (int k = 0; k < 4; k++) {
        float2 fa = __half22float2(pa[k]);
        float2 fb = __half22float2(pb[k]);
        s = fmaf(fa.x, fb.x, s);
        s = fmaf(fa.y, fb.y, s);
    }
    #pragma unroll
    for (int o = 16; o > 0; o >>= 1) s += __shfl_xor_sync(0xffffffffu, s, o);
    if (lane == 0) out[eid] = s;
}

// ---------------- launch ----------------
extern "C" void kernel_launch(void* const* d_in, const int* in_sizes, int n_in,
                              void* d_out, int out_size) {
    const float* x       = (const float*)d_in[0];
    const int*   pos_ei  = (const int*)  d_in[1];
    const int*   ev_ei   = (const int*)  d_in[2];
    const float* Win_W   = (const float*)d_in[3];
    const float* Win_b   = (const float*)d_in[4];
    const float* W1      = (const float*)d_in[5];
    const float* a1_src  = (const float*)d_in[6];
    const float* a1_dst  = (const float*)d_in[7];
    const float* b1      = (const float*)d_in[8];
    const float* W2      = (const float*)d_in[9];
    const float* a2_src  = (const float*)d_in[10];
    const float* a2_dst  = (const float*)d_in[11];
    const float* b2      = (const float*)d_in[12];
    float* out = (float*)d_out;

    float *pAls1, *pAld1, *pAls2, *pAld2, *pBc;
    __half *pXH, *pH1, *pH, *pHO, *pWc, *pW2;
    __nv_bfloat16 *pXh, *pXl, *pW1h, *pW1l;
    cudaGetSymbolAddress((void**)&pXH, g_xH);
    cudaGetSymbolAddress((void**)&pH1, g_h1H);
    cudaGetSymbolAddress((void**)&pH, g_bufH);
    cudaGetSymbolAddress((void**)&pHO, g_hOut);
    cudaGetSymbolAddress((void**)&pAls1, g_als1);
    cudaGetSymbolAddress((void**)&pAld1, g_ald1);
    cudaGetSymbolAddress((void**)&pAls2, g_als2);
    cudaGetSymbolAddress((void**)&pAld2, g_ald2);
    cudaGetSymbolAddress((void**)&pBc, g_bc);
    cudaGetSymbolAddress((void**)&pXh, g_Xh);
    cudaGetSymbolAddress((void**)&pXl, g_Xl);
    cudaGetSymbolAddress((void**)&pW1h, g_W1h);
    cudaGetSymbolAddress((void**)&pW1l, g_W1l);
    cudaGetSymbolAddress((void**)&pWc, g_WcH);
    cudaGetSymbolAddress((void**)&pW2, g_W2H);

    cudaFuncSetAttribute(gemm_fold_kernel,
                         cudaFuncAttributeMaxDynamicSharedMemorySize, SMEM_FOLD);
    cudaFuncSetAttribute(gemm16_kernel,
                         cudaFuncAttributeMaxDynamicSharedMemorySize, SMEM_G16);

    const dim3 ggrid(2, (N_NODES + 63) / 64);
    const dim3 fgrid(2, F / 64);
    const int warps_blocks_n = (N_NODES * 32 + 255) / 256;

    // fused: scatter + x->fp16 + weight splits/converts + fold_bias
    work_kernel<<<WORK_B, 256>>>(pos_ei, x, Win_W, W1, W2, Win_b);

    // fold: Wc = Win_W @ W1 (bf16 3-term) -> fp16 [n][k]
    gemm_fold_kernel<<<fgrid, 256, SMEM_FOLD>>>(pXh, pXl, pW1h, pW1l, F);

    // gemm1: hW1 = x @ Wc + bc -> fp16 + fused al1
    gemm16_kernel<<<ggrid, 256, SMEM_G16>>>(
        pXH, pWc, pBc, a1_src, a1_dst, pAls1, pAld1, pH, N_NODES);
    aggregate_kernel<<<warps_blocks_n, 256>>>(pH, b1, pAls1, pAld1, pH1);

    // gemm2: hW2 = h1 @ W2 -> fp16 + fused al2
    gemm16_kernel<<<ggrid, 256, SMEM_G16>>>(
        pH1, pW2, nullptr, a2_src, a2_dst, pAls2, pAld2, pH, N_NODES);
    aggregate_kernel<<<warps_blocks_n, 256>>>(pH, b2, pAls2, pAld2, pHO);

    // eval logits + state restore
    dot_kernel<<<DOT_B + CLEAN_B, 256>>>(pHO, ev_ei, out);
}